// round 13
// baseline (speedup 1.0000x reference)
#include <cuda_runtime.h>
#include <cuda_fp16.h>

// out[i] = exp(-||x_i-y_i||^2) * net(x_i) * net(y_i)
// net: 9x { z = tanh(z@W^T+b)*s+t } (2->2) folded to z = tanh(Az+c), head 2->1.
//
// R12: R11 (f16x2 layers; MUFU at 37 effective lanes/pair since f16x2 tanh = 2
// MUFU slots) + offload f16-layer #4's tanh to an 8KB smem lerp LUT (LDS pipe).
// MUFU lanes 37 -> 33; issue floor stays well below -> clean MUFU saturation
// at ~117k cyc ~= 64.6us.

#define TPB 256
#define PAIRS 4
#define LUTN 1024
#define LUT_SCALE (1023.0f / 9.0f)   // maps [-4.5, 4.5] -> [0, 1023]
#define LUT_OFF   511.5f

__device__ __forceinline__ float fast_tanh(float x) {
    float y;
    asm("tanh.approx.f32 %0, %1;" : "=f"(y) : "f"(x));
    return y;
}

__device__ __forceinline__ __half2 h2tanh_fast(__half2 v) {
    unsigned r, a = *reinterpret_cast<unsigned*>(&v);
    asm("tanh.approx.f16x2 %0, %1;" : "=r"(r) : "r"(a));
    return *reinterpret_cast<__half2*>(&r);
}

// per-f16-layer params: 4 duplicated weight h2s + 2 duplicated bias h2s (+pad), 32B
struct __align__(16) LayerH {
    __half2 w00, w01, w10, w11;   // (w,w) duplicated
    __half2 c0, c1;               // (c,c) duplicated
    __half2 pad0, pad1;
};

__global__ __launch_bounds__(TPB, 8)
void fraud_kernel(const float2* __restrict__ x2,
                  const float2* __restrict__ y2,
                  const float* __restrict__ W0,
                  const float* __restrict__ b0,
                  const float* __restrict__ scale0,
                  const float* __restrict__ shift0,
                  const float* __restrict__ Ws,
                  const float* __restrict__ bs,
                  const float* __restrict__ scales,
                  const float* __restrict__ shifts,
                  const float* __restrict__ Wf,
                  const float* __restrict__ bf,
                  float* __restrict__ out,
                  int n)
{
    __shared__ LayerH sH[8];          // f16 layers 0..7
    __shared__ float4 sW8;            // f32 layer 8 weights
    __shared__ float2 sC8;            // f32 layer 8 bias
    __shared__ float4 sF4;            // folded head (f0,f1,fb,-)
    __shared__ float2 sLUT[LUTN];     // (tanh(x_i), tanh(x_{i+1})-tanh(x_i)), 8KB

    const int tid = threadIdx.x;

    // fold scale/shift of layer l-1 into layer l's (W,b); head folds layer 8's.
    if (tid < 9) {
        const float* W = (tid == 0) ? W0 : (Ws + (tid - 1) * 4);
        const float* B = (tid == 0) ? b0 : (bs + (tid - 1) * 2);
        float ps0 = 1.f, ps1 = 1.f, pt0 = 0.f, pt1 = 0.f;
        if (tid == 1) {
            ps0 = scale0[0]; ps1 = scale0[1];
            pt0 = shift0[0]; pt1 = shift0[1];
        } else if (tid >= 2) {
            ps0 = scales[(tid - 2) * 2 + 0]; ps1 = scales[(tid - 2) * 2 + 1];
            pt0 = shifts[(tid - 2) * 2 + 0]; pt1 = shifts[(tid - 2) * 2 + 1];
        }
        float w00 = W[0] * ps0, w01 = W[1] * ps1;
        float w10 = W[2] * ps0, w11 = W[3] * ps1;
        float c0 = B[0] + W[0] * pt0 + W[1] * pt1;
        float c1 = B[1] + W[2] * pt0 + W[3] * pt1;

        if (tid < 8) {
            LayerH L;
            L.w00 = __float2half2_rn(w00);
            L.w01 = __float2half2_rn(w01);
            L.w10 = __float2half2_rn(w10);
            L.w11 = __float2half2_rn(w11);
            L.c0  = __float2half2_rn(c0);
            L.c1  = __float2half2_rn(c1);
            L.pad0 = __float2half2_rn(0.f);
            L.pad1 = __float2half2_rn(0.f);
            sH[tid] = L;
        } else {
            float4 wf; wf.x = w00; wf.y = w01; wf.z = w10; wf.w = w11;
            sW8 = wf;
            float2 cf; cf.x = c0; cf.y = c1;
            sC8 = cf;
        }
    } else if (tid == 9) {
        float s0 = scales[14], s1 = scales[15];
        float t0 = shifts[14], t1 = shifts[15];
        float4 f;
        f.x = Wf[0] * s0;
        f.y = Wf[1] * s1;
        f.z = bf[0] + Wf[0] * t0 + Wf[1] * t1;
        f.w = 0.f;
        sF4 = f;
    }

    // build tanh lerp LUT (accurate tanhf; amortized over 1024 pairs/block)
    for (int e = tid; e < LUTN; e += TPB) {
        float x0 = -4.5f + (float)e * (9.0f / 1023.0f);
        float x1 = -4.5f + (float)(e + 1) * (9.0f / 1023.0f);
        float y0 = tanhf(x0);
        float y1 = tanhf(x1);
        float2 v; v.x = y0; v.y = y1 - y0;
        sLUT[e] = v;
    }
    __syncthreads();

    const __half2 hLo = __floats2half2_rn(-4.5f, -4.5f);
    const __half2 hHi = __floats2half2_rn(4.5f, 4.5f);

    int i = blockIdx.x * (TPB * PAIRS) + tid;

    #pragma unroll 1
    for (int p = 0; p < PAIRS; p++, i += TPB) {
        if (i < n) {
            float2 xv = x2[i];
            float2 yv = y2[i];

            float dx = xv.x - yv.x;
            float dy = xv.y - yv.y;
            float rbf = __expf(-fmaf(dx, dx, dy * dy));

            // halves = (net(x), net(y)); z0 = unit0, z1 = unit1
            __half2 z0 = __floats2half2_rn(xv.x, yv.x);
            __half2 z1 = __floats2half2_rn(xv.y, yv.y);

            // layers 0..3 on MUFU (f16x2)
            #pragma unroll 1
            for (int l = 0; l < 4; l++) {
                const LayerH L = sH[l];
                __half2 u0 = __hfma2(z0, L.w00, __hfma2(z1, L.w01, L.c0));
                __half2 u1 = __hfma2(z0, L.w10, __hfma2(z1, L.w11, L.c1));
                z0 = h2tanh_fast(u0);
                z1 = h2tanh_fast(u1);
            }

            // layer 4: tanh via smem lerp LUT (LDS + FMA pipes, no MUFU)
            {
                const LayerH L = sH[4];
                __half2 u0 = __hfma2(z0, L.w00, __hfma2(z1, L.w01, L.c0));
                __half2 u1 = __hfma2(z0, L.w10, __hfma2(z1, L.w11, L.c1));
                u0 = __hmax2(__hmin2(u0, hHi), hLo);
                u1 = __hmax2(__hmin2(u1, hHi), hLo);
                float2 f0 = __half22float2(u0);
                float2 f1 = __half22float2(u1);

                float uf, fl, fr;
                int ii;

                uf = fmaf(f0.x, LUT_SCALE, LUT_OFF);
                ii = __float2int_rd(uf); fl = (float)ii; fr = uf - fl;
                float2 e00 = sLUT[ii];
                float r00 = fmaf(fr, e00.y, e00.x);

                uf = fmaf(f0.y, LUT_SCALE, LUT_OFF);
                ii = __float2int_rd(uf); fl = (float)ii; fr = uf - fl;
                float2 e01 = sLUT[ii];
                float r01 = fmaf(fr, e01.y, e01.x);

                uf = fmaf(f1.x, LUT_SCALE, LUT_OFF);
                ii = __float2int_rd(uf); fl = (float)ii; fr = uf - fl;
                float2 e10 = sLUT[ii];
                float r10 = fmaf(fr, e10.y, e10.x);

                uf = fmaf(f1.y, LUT_SCALE, LUT_OFF);
                ii = __float2int_rd(uf); fl = (float)ii; fr = uf - fl;
                float2 e11 = sLUT[ii];
                float r11 = fmaf(fr, e11.y, e11.x);

                z0 = __floats2half2_rn(r00, r01);
                z1 = __floats2half2_rn(r10, r11);
            }

            // layers 5..7 on MUFU (f16x2)
            #pragma unroll 1
            for (int l = 5; l < 8; l++) {
                const LayerH L = sH[l];
                __half2 u0 = __hfma2(z0, L.w00, __hfma2(z1, L.w01, L.c0));
                __half2 u1 = __hfma2(z0, L.w10, __hfma2(z1, L.w11, L.c1));
                z0 = h2tanh_fast(u0);
                z1 = h2tanh_fast(u1);
            }

            // unpack; layer 8 + head in f32
            float ax0 = __low2float(z0),  ay0 = __high2float(z0);
            float ax1 = __low2float(z1),  ay1 = __high2float(z1);

            float4 W = sW8;
            float2 C = sC8;
            float ux0 = fmaf(ax0, W.x, fmaf(ax1, W.y, C.x));
            float ux1 = fmaf(ax0, W.z, fmaf(ax1, W.w, C.y));
            float uy0 = fmaf(ay0, W.x, fmaf(ay1, W.y, C.x));
            float uy1 = fmaf(ay0, W.z, fmaf(ay1, W.w, C.y));
            ax0 = fast_tanh(ux0); ax1 = fast_tanh(ux1);
            ay0 = fast_tanh(uy0); ay1 = fast_tanh(uy1);

            float4 F = sF4;
            float fx = fmaf(ax0, F.x, fmaf(ax1, F.y, F.z));
            float fy = fmaf(ay0, F.x, fmaf(ay1, F.y, F.z));

            out[i] = rbf * fx * fy;
        }
    }
}

extern "C" void kernel_launch(void* const* d_in, const int* in_sizes, int n_in,
                              void* d_out, int out_size)
{
    const float2* x2     = (const float2*)d_in[0];
    const float2* y2     = (const float2*)d_in[1];
    const float*  W0     = (const float*)d_in[2];
    const float*  b0     = (const float*)d_in[3];
    const float*  scale0 = (const float*)d_in[4];
    const float*  shift0 = (const float*)d_in[5];
    const float*  Ws     = (const float*)d_in[6];
    const float*  bs     = (const float*)d_in[7];
    const float*  scales = (const float*)d_in[8];
    const float*  shifts = (const float*)d_in[9];
    const float*  Wf     = (const float*)d_in[10];
    const float*  bf     = (const float*)d_in[11];
    float* out = (float*)d_out;

    int n = in_sizes[0] / 2;            // pairs
    int per_block = TPB * PAIRS;
    int blocks = (n + per_block - 1) / per_block;

    fraud_kernel<<<blocks, TPB>>>(x2, y2, W0, b0, scale0, shift0,
                                  Ws, bs, scales, shifts, Wf, bf, out, n);
}

// round 17
// speedup vs baseline: 1.1546x; 1.1546x over previous
#include <cuda_runtime.h>
#include <cuda_fp16.h>

// out[i] = exp(-||x_i-y_i||^2) * net(x_i) * net(y_i)
// net: 9x { z = tanh(z@W^T+b)*s+t } folded to z = tanh(Az+c), head 2->1.
//
// R16 (= R14 resubmit; prior round died to a broker infra failure, kernel never ran):
// layers 0..6 f16x2 MUFU tanh (28 lanes), layers 7..8 f32 with a lean smem
// lerp-LUT tanh (7 instr/scalar, fixed-point magic indexing, (a,b) line coeffs).
// MUFU lanes 37 -> ~30 => floor ~106k cyc (~58us). 2 pairs/thread amortizes
// weight LDS + loop overhead so issue (~63k) and LSU (~66k) stay far below MUFU.

#define TPB 256
#define ITERS 4              // 4 iterations x 2 pairs = 8 pairs/thread
#define LUTN 1024
#define LUT_S 113.77777778f  // 1024/9
#define LUT_H 0.0087890625f  // 9/1024
#define LUT_BIG 12583424.0f  // 1.5*2^23 + 512
#define LUT_CLAMP 4.4912f

__device__ __forceinline__ float fast_tanh(float x) {
    float y;
    asm("tanh.approx.f32 %0, %1;" : "=f"(y) : "f"(x));
    return y;
}

__device__ __forceinline__ __half2 h2tanh_fast(__half2 v) {
    unsigned r, a = *reinterpret_cast<unsigned*>(&v);
    asm("tanh.approx.f16x2 %0, %1;" : "=r"(r) : "r"(a));
    return *reinterpret_cast<__half2*>(&r);
}

// lean LUT tanh: 2 FMNMX + 1 FFMA.RZ + 1 LOP + 1 IMAD(addr) + 1 LDS.64 + 1 FFMA
__device__ __forceinline__ float lut_tanh(float u, const float2* __restrict__ sLUT) {
    u = fminf(fmaxf(u, -LUT_CLAMP), LUT_CLAMP);
    float t = __fmaf_rz(u, LUT_S, LUT_BIG);      // 12582912 + (512 + floor(u*S))
    int idx = __float_as_int(t) & 0x3FF;         // 512 + floor(u*S)  in [1,1023]
    float2 e = sLUT[idx];
    return fmaf(u, e.y, e.x);                    // a + b*u
}

struct __align__(16) LayerH {
    __half2 w00, w01, w10, w11;   // (w,w) duplicated
    __half2 c0, c1;               // (c,c) duplicated
    __half2 pad0, pad1;
};

__global__ __launch_bounds__(TPB, 6)
void fraud_kernel(const float4* __restrict__ x4,
                  const float4* __restrict__ y4,
                  const float* __restrict__ W0,
                  const float* __restrict__ b0,
                  const float* __restrict__ scale0,
                  const float* __restrict__ shift0,
                  const float* __restrict__ Ws,
                  const float* __restrict__ bs,
                  const float* __restrict__ scales,
                  const float* __restrict__ shifts,
                  const float* __restrict__ Wf,
                  const float* __restrict__ bf,
                  float* __restrict__ out,
                  int n)
{
    __shared__ LayerH sH[7];          // f16 layers 0..6
    __shared__ float4 sW7, sW8;       // f32 layers 7, 8 weights
    __shared__ float2 sC7, sC8;       // f32 layers 7, 8 biases
    __shared__ float4 sF4;            // folded head (f0,f1,fb,-)
    __shared__ float2 sLUT[LUTN];     // per-interval (a, b): tanh ~= a + b*u
    __shared__ float4 sWf[9];         // f32 folded weights (tail fallback)
    __shared__ float2 sCf[9];

    const int tid = threadIdx.x;

    // fold scale/shift of layer l-1 into layer l's (W,b); head folds layer 8's.
    if (tid < 9) {
        const float* W = (tid == 0) ? W0 : (Ws + (tid - 1) * 4);
        const float* B = (tid == 0) ? b0 : (bs + (tid - 1) * 2);
        float ps0 = 1.f, ps1 = 1.f, pt0 = 0.f, pt1 = 0.f;
        if (tid == 1) {
            ps0 = scale0[0]; ps1 = scale0[1];
            pt0 = shift0[0]; pt1 = shift0[1];
        } else if (tid >= 2) {
            ps0 = scales[(tid - 2) * 2 + 0]; ps1 = scales[(tid - 2) * 2 + 1];
            pt0 = shifts[(tid - 2) * 2 + 0]; pt1 = shifts[(tid - 2) * 2 + 1];
        }
        float w00 = W[0] * ps0, w01 = W[1] * ps1;
        float w10 = W[2] * ps0, w11 = W[3] * ps1;
        float c0 = B[0] + W[0] * pt0 + W[1] * pt1;
        float c1 = B[1] + W[2] * pt0 + W[3] * pt1;

        float4 wf; wf.x = w00; wf.y = w01; wf.z = w10; wf.w = w11;
        sWf[tid] = wf;
        float2 cf; cf.x = c0; cf.y = c1;
        sCf[tid] = cf;

        if (tid < 7) {
            LayerH L;
            L.w00 = __float2half2_rn(w00);
            L.w01 = __float2half2_rn(w01);
            L.w10 = __float2half2_rn(w10);
            L.w11 = __float2half2_rn(w11);
            L.c0  = __float2half2_rn(c0);
            L.c1  = __float2half2_rn(c1);
            L.pad0 = __float2half2_rn(0.f);
            L.pad1 = __float2half2_rn(0.f);
            sH[tid] = L;
        } else if (tid == 7) {
            sW7 = wf; sC7 = cf;
        } else {
            sW8 = wf; sC8 = cf;
        }
    } else if (tid == 9) {
        float s0 = scales[14], s1 = scales[15];
        float t0 = shifts[14], t1 = shifts[15];
        float4 f;
        f.x = Wf[0] * s0;
        f.y = Wf[1] * s1;
        f.z = bf[0] + Wf[0] * t0 + Wf[1] * t1;
        f.w = 0.f;
        sF4 = f;
    }

    // build tanh line-coefficient LUT: y = a + b*u on [x0, x0+h)
    #pragma unroll
    for (int e = tid; e < LUTN; e += TPB) {
        float x0 = fmaf((float)e, LUT_H, -4.5f);
        float y0 = fast_tanh(x0);
        float y1 = fast_tanh(x0 + LUT_H);
        float b = (y1 - y0) * LUT_S;
        float2 v; v.x = fmaf(-x0, b, y0); v.y = b;
        sLUT[e] = v;
    }
    __syncthreads();

    int f = blockIdx.x * (TPB * ITERS) + tid;   // float4 index = 2 pairs

    #pragma unroll 1
    for (int it = 0; it < ITERS; it++, f += TPB) {
        int p0 = 2 * f;
        if (p0 + 1 < n) {
            float4 xa = x4[f];
            float4 ya = y4[f];

            float dxA = xa.x - ya.x, dyA = xa.y - ya.y;
            float dxB = xa.z - ya.z, dyB = xa.w - ya.w;
            float rbfA = __expf(-fmaf(dxA, dxA, dyA * dyA));
            float rbfB = __expf(-fmaf(dxB, dxB, dyB * dyB));

            // per pair: halves = (net(x), net(y))
            __half2 zA0 = __floats2half2_rn(xa.x, ya.x);
            __half2 zA1 = __floats2half2_rn(xa.y, ya.y);
            __half2 zB0 = __floats2half2_rn(xa.z, ya.z);
            __half2 zB1 = __floats2half2_rn(xa.w, ya.w);

            // layers 0..6 in f16x2 (per layer: 8 HFMA2 + 4 MUFU for 2 pairs)
            #pragma unroll 1
            for (int l = 0; l < 7; l++) {
                const LayerH L = sH[l];
                __half2 uA0 = __hfma2(zA0, L.w00, __hfma2(zA1, L.w01, L.c0));
                __half2 uA1 = __hfma2(zA0, L.w10, __hfma2(zA1, L.w11, L.c1));
                __half2 uB0 = __hfma2(zB0, L.w00, __hfma2(zB1, L.w01, L.c0));
                __half2 uB1 = __hfma2(zB0, L.w10, __hfma2(zB1, L.w11, L.c1));
                zA0 = h2tanh_fast(uA0);
                zA1 = h2tanh_fast(uA1);
                zB0 = h2tanh_fast(uB0);
                zB1 = h2tanh_fast(uB1);
            }

            // unpack to f32: per pair (x-net unit0/1, y-net unit0/1)
            float xA0 = __low2float(zA0), yA0 = __high2float(zA0);
            float xA1 = __low2float(zA1), yA1 = __high2float(zA1);
            float xB0 = __low2float(zB0), yB0 = __high2float(zB0);
            float xB1 = __low2float(zB1), yB1 = __high2float(zB1);

            // layer 7: f32 affine + LUT tanh
            {
                float4 W = sW7; float2 C = sC7;
                float u;
                u = fmaf(xA0, W.x, fmaf(xA1, W.y, C.x));
                float v = fmaf(xA0, W.z, fmaf(xA1, W.w, C.y));
                xA0 = lut_tanh(u, sLUT); xA1 = lut_tanh(v, sLUT);
                u = fmaf(yA0, W.x, fmaf(yA1, W.y, C.x));
                v = fmaf(yA0, W.z, fmaf(yA1, W.w, C.y));
                yA0 = lut_tanh(u, sLUT); yA1 = lut_tanh(v, sLUT);
                u = fmaf(xB0, W.x, fmaf(xB1, W.y, C.x));
                v = fmaf(xB0, W.z, fmaf(xB1, W.w, C.y));
                xB0 = lut_tanh(u, sLUT); xB1 = lut_tanh(v, sLUT);
                u = fmaf(yB0, W.x, fmaf(yB1, W.y, C.x));
                v = fmaf(yB0, W.z, fmaf(yB1, W.w, C.y));
                yB0 = lut_tanh(u, sLUT); yB1 = lut_tanh(v, sLUT);
            }

            // layer 8: f32 affine + LUT tanh
            {
                float4 W = sW8; float2 C = sC8;
                float u, v;
                u = fmaf(xA0, W.x, fmaf(xA1, W.y, C.x));
                v = fmaf(xA0, W.z, fmaf(xA1, W.w, C.y));
                xA0 = lut_tanh(u, sLUT); xA1 = lut_tanh(v, sLUT);
                u = fmaf(yA0, W.x, fmaf(yA1, W.y, C.x));
                v = fmaf(yA0, W.z, fmaf(yA1, W.w, C.y));
                yA0 = lut_tanh(u, sLUT); yA1 = lut_tanh(v, sLUT);
                u = fmaf(xB0, W.x, fmaf(xB1, W.y, C.x));
                v = fmaf(xB0, W.z, fmaf(xB1, W.w, C.y));
                xB0 = lut_tanh(u, sLUT); xB1 = lut_tanh(v, sLUT);
                u = fmaf(yB0, W.x, fmaf(yB1, W.y, C.x));
                v = fmaf(yB0, W.z, fmaf(yB1, W.w, C.y));
                yB0 = lut_tanh(u, sLUT); yB1 = lut_tanh(v, sLUT);
            }

            float4 F = sF4;
            float fxA = fmaf(xA0, F.x, fmaf(xA1, F.y, F.z));
            float fyA = fmaf(yA0, F.x, fmaf(yA1, F.y, F.z));
            float fxB = fmaf(xB0, F.x, fmaf(xB1, F.y, F.z));
            float fyB = fmaf(yB0, F.x, fmaf(yB1, F.y, F.z));

            float2 r;
            r.x = rbfA * fxA * fyA;
            r.y = rbfB * fxB * fyB;
            reinterpret_cast<float2*>(out)[f] = r;
        } else if (p0 < n) {
            // tail: single pair, all-f32 MUFU path
            const float2* x2p = reinterpret_cast<const float2*>(x4);
            const float2* y2p = reinterpret_cast<const float2*>(y4);
            float2 xv = x2p[p0], yv = y2p[p0];
            float dx = xv.x - yv.x, dy = xv.y - yv.y;
            float rbf = __expf(-fmaf(dx, dx, dy * dy));
            float a0 = xv.x, a1 = xv.y, b0 = yv.x, b1 = yv.y;
            #pragma unroll 1
            for (int l = 0; l < 9; l++) {
                float4 W = sWf[l];
                float2 C = sCf[l];
                float u0 = fmaf(a0, W.x, fmaf(a1, W.y, C.x));
                float u1 = fmaf(a0, W.z, fmaf(a1, W.w, C.y));
                float v0 = fmaf(b0, W.x, fmaf(b1, W.y, C.x));
                float v1 = fmaf(b0, W.z, fmaf(b1, W.w, C.y));
                a0 = fast_tanh(u0); a1 = fast_tanh(u1);
                b0 = fast_tanh(v0); b1 = fast_tanh(v1);
            }
            float4 F = sF4;
            float fx = fmaf(a0, F.x, fmaf(a1, F.y, F.z));
            float fy = fmaf(b0, F.x, fmaf(b1, F.y, F.z));
            out[p0] = rbf * fx * fy;
        }
    }
}

extern "C" void kernel_launch(void* const* d_in, const int* in_sizes, int n_in,
                              void* d_out, int out_size)
{
    const float4* x4     = (const float4*)d_in[0];
    const float4* y4     = (const float4*)d_in[1];
    const float*  W0     = (const float*)d_in[2];
    const float*  b0     = (const float*)d_in[3];
    const float*  scale0 = (const float*)d_in[4];
    const float*  shift0 = (const float*)d_in[5];
    const float*  Ws     = (const float*)d_in[6];
    const float*  bs     = (const float*)d_in[7];
    const float*  scales = (const float*)d_in[8];
    const float*  shifts = (const float*)d_in[9];
    const float*  Wf     = (const float*)d_in[10];
    const float*  bf     = (const float*)d_in[11];
    float* out = (float*)d_out;

    int n = in_sizes[0] / 2;               // pairs
    int per_block = TPB * ITERS * 2;       // 8 pairs per thread
    int blocks = (n + per_block - 1) / per_block;

    fraud_kernel<<<blocks, TPB>>>(x4, y4, W0, b0, scale0, shift0,
                                  Ws, bs, scales, shifts, Wf, bf, out, n);
}